// round 4
// baseline (speedup 1.0000x reference)
#include <cuda_runtime.h>

// diff_pred: 16-tap LPC FIR with mu-law decode/encode.
//   sig: (2048, 2400, 1) float32, values in [0, 255]
//   lpc: (2048, 15, 16)  float32  (one 16-tap filter per 160-sample frame)
//   out: (2048, 2400, 1) float32 = l2u( -sum_j lpc[b, t/160, j] * u2l(sig)[b, t-j] )
//
// One block per (batch, frame): 160 threads decode 160 samples + 16 halo
// samples into smem once (amortizing the exp2 across all 16 windows that
// touch each sample), then each thread computes a fully unrolled 16-tap dot.

#define FRAME_LEN 160
#define NTAPS     16
#define T_LEN     2400
#define NFRAMES   15   // T_LEN / FRAME_LEN

__global__ __launch_bounds__(FRAME_LEN)
void diff_pred_79336635892364_kernel(const float* __restrict__ sig,
                                     const float* __restrict__ lpc,
                                     float* __restrict__ out)
{
    __shared__ float xt_s[FRAME_LEN + NTAPS];
    __shared__ float lpc_s[NTAPS];

    const float SCALE_INV = 32768.0f / 255.0f;   // SCALE_1
    const float SCALE     = 255.0f / 32768.0f;

    const int bid   = blockIdx.x;
    const int batch = bid / NFRAMES;
    const int frame = bid - batch * NFRAMES;
    const int tid   = threadIdx.x;
    const int t0    = frame * FRAME_LEN;

    const float* __restrict__ srow = sig + (size_t)batch * T_LEN;

    // --- mu-law decode: u2l(u) = sign(u-128) * (32768/255) * (2^(|u-128|/16) - 1)
    {
        float u = srow[t0 + tid] - 128.0f;
        float a = fabsf(u);
        float m = SCALE_INV * (exp2f(a * 0.0625f) - 1.0f);
        xt_s[NTAPS + tid] = copysignf(m, u);   // m==0 when u==0, matches sign(0)=0
    }
    if (tid < NTAPS) {
        // halo: previous 16 samples (zero-padded at sequence start)
        int th = t0 - NTAPS + tid;
        float xh = 0.0f;
        if (th >= 0) {
            float u = srow[th] - 128.0f;
            float a = fabsf(u);
            xh = copysignf(SCALE_INV * (exp2f(a * 0.0625f) - 1.0f), u);
        }
        xt_s[tid] = xh;
        lpc_s[tid] = lpc[((size_t)batch * NFRAMES + frame) * NTAPS + tid];
    }
    __syncthreads();

    // --- 16-tap FIR: pred[t] = -sum_j lpc[j] * xt[t - j]
    float acc = 0.0f;
    #pragma unroll
    for (int j = 0; j < NTAPS; j++) {
        acc = fmaf(lpc_s[j], xt_s[NTAPS + tid - j], acc);
    }
    float p = -acc;

    // --- mu-law encode: l2u(p) = clip(128 + sign(p)*16*log2(1 + SCALE*|p|), 0, 255)
    float ap = fabsf(p);
    float uo = copysignf(16.0f * __log2f(fmaf(SCALE, ap, 1.0f)), p);
    float r  = 128.0f + uo;
    r = fminf(fmaxf(r, 0.0f), 255.0f);

    out[(size_t)batch * T_LEN + t0 + tid] = r;
}

extern "C" void kernel_launch(void* const* d_in, const int* in_sizes, int n_in,
                              void* d_out, int out_size)
{
    const float* sig = (const float*)d_in[0];  // (2048, 2400, 1) fp32
    const float* lpc = (const float*)d_in[1];  // (2048, 15, 16)  fp32
    float* out = (float*)d_out;                // (2048, 2400, 1) fp32

    const int batches = in_sizes[0] / T_LEN;   // 2048
    dim3 grid(batches * NFRAMES);              // 30720 blocks
    dim3 block(FRAME_LEN);                     // 160 threads
    diff_pred_79336635892364_kernel<<<grid, block>>>(sig, lpc, out);
}

// round 8
// speedup vs baseline: 2.2804x; 2.2804x over previous
#include <cuda_runtime.h>

// diff_pred: 16-tap LPC FIR with mu-law decode/encode, register-resident.
//   sig: (2048, 2400, 1) fp32   lpc: (2048, 15, 16) fp32   out: (2048, 2400, 1) fp32
//
// Each thread produces 16 consecutive outputs (one 16-sample segment, always
// inside a single 160-sample frame). It loads the 32 inputs it needs as 8
// float4, decodes them once, and runs a fully unrolled 16x16 FIR entirely in
// registers. No shared memory, no __syncthreads.

#define NTAPS     16
#define T_LEN     2400
#define FRAME_LEN 160
#define NFRAMES   15
#define OPT       16              // outputs per thread
#define SEGS      (T_LEN / OPT)   // 150 segments per batch row

__device__ __forceinline__ float ex2_fast(float a) {
    float r;
    asm("ex2.approx.ftz.f32 %0, %1;" : "=f"(r) : "f"(a));
    return r;
}

__global__ __launch_bounds__(256)
void diff_pred_79336635892364_kernel(const float* __restrict__ sig,
                                     const float* __restrict__ lpc,
                                     float* __restrict__ out)
{
    const float SINV = 32768.0f / 255.0f;   // SCALE_1
    const float SC   = 255.0f / 32768.0f;   // SCALE

    const int g     = blockIdx.x * blockDim.x + threadIdx.x;
    const int batch = g / SEGS;
    const int seg   = g - batch * SEGS;
    const int t0    = seg * OPT;

    const float* __restrict__ srow = sig + (size_t)batch * T_LEN;

    // ---- load 32 raw samples [t0-16, t0+16) as 8 float4 (64B aligned) ----
    float raw[32];
    float4* rv = reinterpret_cast<float4*>(raw);
    if (seg == 0) {
        // left padding: raw value 128 decodes to exactly 0
        #pragma unroll
        for (int i = 0; i < 4; i++) rv[i] = make_float4(128.f, 128.f, 128.f, 128.f);
        const float4* sp0 = reinterpret_cast<const float4*>(srow);
        #pragma unroll
        for (int i = 0; i < 4; i++) rv[4 + i] = sp0[i];
    } else {
        const float4* sp = reinterpret_cast<const float4*>(srow + t0 - NTAPS);
        #pragma unroll
        for (int i = 0; i < 8; i++) rv[i] = sp[i];
    }

    // ---- mu-law decode: u2l(u) = copysign(SINV*(2^(|u-128|/16) - 1), u-128) ----
    float x[32];
    #pragma unroll
    for (int k = 0; k < 32; k++) {
        float u = raw[k] - 128.0f;
        float e = ex2_fast(fabsf(u) * 0.0625f);
        float m = fmaf(SINV, e, -SINV);
        x[k] = copysignf(m, u);
    }

    // ---- lpc coefficients for this frame (warp-mostly-uniform, L1 broadcast) ----
    const int frame = seg / (FRAME_LEN / OPT);   // seg / 10
    float c[NTAPS];
    {
        const float4* lp = reinterpret_cast<const float4*>(
            lpc + ((size_t)batch * NFRAMES + frame) * NTAPS);
        float4* cv = reinterpret_cast<float4*>(c);
        #pragma unroll
        for (int i = 0; i < 4; i++) cv[i] = lp[i];
    }

    // ---- 16x16 register FIR: pred[i] = -sum_j c[j] * x[16 + i - j] ----
    float acc[OPT];
    #pragma unroll
    for (int i = 0; i < OPT; i++) acc[i] = 0.0f;
    #pragma unroll
    for (int j = 0; j < NTAPS; j++) {
        #pragma unroll
        for (int i = 0; i < OPT; i++)
            acc[i] = fmaf(c[j], x[NTAPS + i - j], acc[i]);
    }

    // ---- mu-law encode: l2u(p) = clip(128 + copysign(16*log2(1+SC*|p|), p), 0, 255) ----
    float res[OPT];
    #pragma unroll
    for (int i = 0; i < OPT; i++) {
        float p  = -acc[i];
        float uo = copysignf(16.0f * __log2f(fmaf(SC, fabsf(p), 1.0f)), p);
        res[i]   = fminf(fmaxf(128.0f + uo, 0.0f), 255.0f);
    }

    // ---- vector store ----
    float4* ov = reinterpret_cast<float4*>(out + (size_t)batch * T_LEN + t0);
    const float4* rr = reinterpret_cast<const float4*>(res);
    #pragma unroll
    for (int i = 0; i < 4; i++) ov[i] = rr[i];
}

extern "C" void kernel_launch(void* const* d_in, const int* in_sizes, int n_in,
                              void* d_out, int out_size)
{
    const float* sig = (const float*)d_in[0];
    const float* lpc = (const float*)d_in[1];
    float* out = (float*)d_out;

    const int batches = in_sizes[0] / T_LEN;           // 2048
    const int total_threads = batches * SEGS;          // 307200
    dim3 block(256);
    dim3 grid((total_threads + 255) / 256);            // 1200
    diff_pred_79336635892364_kernel<<<grid, block>>>(sig, lpc, out);
}

// round 9
// speedup vs baseline: 2.3735x; 1.0409x over previous
#include <cuda_runtime.h>

// diff_pred: 16-tap LPC FIR with mu-law decode/encode.
//   sig: (2048, 2400, 1) fp32   lpc: (2048, 15, 16) fp32   out: (2048, 2400, 1) fp32
//
// Each thread produces 16 consecutive outputs. It decodes only its OWN 16
// samples (4x LDG.128), publishes them to padded shared memory, and fetches
// its 16-tap halo from the previous thread's slot (4x LDS.128, conflict-free
// via 20-float stride). Only tid==0 per block re-loads/decodes its halo from
// global; row-start segments use an exact zero halo. FIR is a fully unrolled
// 16x16 register kernel.

#define NTAPS     16
#define T_LEN     2400
#define NFRAMES   15
#define OPT       16
#define SEGS      (T_LEN / OPT)    // 150 segments per row
#define SLOT      20               // padded smem floats per thread (bank-conflict-free)

__device__ __forceinline__ float ex2_fast(float a) {
    float r;
    asm("ex2.approx.ftz.f32 %0, %1;" : "=f"(r) : "f"(a));
    return r;
}

// mu-law decode: u2l(raw) = copysign(SINV*(2^(|raw-128|/16) - 1), raw-128)
//   t = raw/16 - 8  has the same sign and 16x-scaled magnitude as raw-128.
__device__ __forceinline__ float u2l_fast(float raw) {
    const float SINV = 32768.0f / 255.0f;
    float t = fmaf(raw, 0.0625f, -8.0f);       // FFMA-imm (double-rate)
    float e = ex2_fast(fabsf(t));              // abs = free src modifier
    float m = fmaf(SINV, e, -SINV);
    return copysignf(m, t);                    // single LOP3
}

__global__ __launch_bounds__(256)
void diff_pred_79336635892364_kernel(const float* __restrict__ sig,
                                     const float* __restrict__ lpc,
                                     float* __restrict__ out)
{
    __shared__ float xs[256 * SLOT];

    const float SC = 255.0f / 32768.0f;

    const int tid   = threadIdx.x;
    const int g     = blockIdx.x * blockDim.x + tid;
    const int batch = g / SEGS;
    const int seg   = g - batch * SEGS;
    const int t0    = seg * OPT;

    const float* __restrict__ srow = sig + (size_t)batch * T_LEN;

    // ---- load own 16 raw samples (64B-aligned) + lpc coeffs (batch the LDGs) ----
    float raw[OPT];
    {
        const float4* sp = reinterpret_cast<const float4*>(srow + t0);
        float4* rv = reinterpret_cast<float4*>(raw);
        #pragma unroll
        for (int i = 0; i < 4; i++) rv[i] = sp[i];
    }
    const int frame = seg / (160 / OPT);       // seg / 10
    float c[NTAPS];
    {
        const float4* lp = reinterpret_cast<const float4*>(
            lpc + ((size_t)batch * NFRAMES + frame) * NTAPS);
        float4* cv = reinterpret_cast<float4*>(c);
        #pragma unroll
        for (int i = 0; i < 4; i++) cv[i] = lp[i];
    }

    // ---- decode own samples into xw[16..31] and publish to smem ----
    float xw[2 * NTAPS];
    #pragma unroll
    for (int k = 0; k < OPT; k++) xw[NTAPS + k] = u2l_fast(raw[k]);

    {
        float4* slot = reinterpret_cast<float4*>(xs + tid * SLOT);
        const float4* ov = reinterpret_cast<const float4*>(&xw[NTAPS]);
        #pragma unroll
        for (int i = 0; i < 4; i++) slot[i] = ov[i];
    }
    __syncthreads();

    // ---- halo xw[0..15] = decoded previous segment ----
    if (seg == 0) {
        // row start: zero-padded history (u2l(128) == 0 exactly)
        #pragma unroll
        for (int k = 0; k < NTAPS; k++) xw[k] = 0.0f;
    } else if (tid == 0) {
        // cross-block: re-load + decode from global (once per block)
        const float4* sp = reinterpret_cast<const float4*>(srow + t0 - NTAPS);
        float hraw[NTAPS];
        float4* hv = reinterpret_cast<float4*>(hraw);
        #pragma unroll
        for (int i = 0; i < 4; i++) hv[i] = sp[i];
        #pragma unroll
        for (int k = 0; k < NTAPS; k++) xw[k] = u2l_fast(hraw[k]);
    } else {
        const float4* hs = reinterpret_cast<const float4*>(xs + (tid - 1) * SLOT);
        float4* hv = reinterpret_cast<float4*>(xw);
        #pragma unroll
        for (int i = 0; i < 4; i++) hv[i] = hs[i];
    }

    // ---- 16x16 register FIR: pred[i] = -sum_j c[j] * xw[16 + i - j] ----
    float acc[OPT];
    #pragma unroll
    for (int i = 0; i < OPT; i++) acc[i] = 0.0f;
    #pragma unroll
    for (int j = 0; j < NTAPS; j++) {
        #pragma unroll
        for (int i = 0; i < OPT; i++)
            acc[i] = fmaf(c[j], xw[NTAPS + i - j], acc[i]);
    }

    // ---- mu-law encode: l2u(-acc) = clip(128 + copysign(16*log2(1+SC*|acc|), -acc), 0, 255)
    float res[OPT];
    #pragma unroll
    for (int i = 0; i < OPT; i++) {
        float a  = acc[i];
        float v  = 16.0f * __log2f(fmaf(SC, fabsf(a), 1.0f));
        float uo = copysignf(v, -a);           // sign(-acc): one LOP3
        res[i]   = fminf(fmaxf(128.0f + uo, 0.0f), 255.0f);
    }

    // ---- vector store ----
    float4* ovp = reinterpret_cast<float4*>(out + (size_t)batch * T_LEN + t0);
    const float4* rr = reinterpret_cast<const float4*>(res);
    #pragma unroll
    for (int i = 0; i < 4; i++) ovp[i] = rr[i];
}

extern "C" void kernel_launch(void* const* d_in, const int* in_sizes, int n_in,
                              void* d_out, int out_size)
{
    const float* sig = (const float*)d_in[0];
    const float* lpc = (const float*)d_in[1];
    float* out = (float*)d_out;

    const int batches = in_sizes[0] / T_LEN;          // 2048
    const int total_threads = batches * SEGS;         // 307200
    dim3 block(256);
    dim3 grid((total_threads + 255) / 256);           // 1200 (exact)
    diff_pred_79336635892364_kernel<<<grid, block>>>(sig, lpc, out);
}